// round 3
// baseline (speedup 1.0000x reference)
#include <cuda_runtime.h>
#include <math.h>

#define Bb 64
#define Tt 20
#define Cc 512
#define HW 196
#define Vv 10000
#define Ee 256
#define Uu 512
#define Gg 2048   // 4*U
#define Oo 1280   // U + C + E

// ---------------- scratch (device globals; no runtime allocation) -------------
__device__ float g_mean[Bb * Cc];
__device__ float g_hid[Bb * Uu];
__device__ float g_cell[Bb * Uu];
__device__ float g_q[Bb * Cc];
__device__ float g_a[Bb * Cc];
__device__ float g_P[Bb * Tt * Gg];        // precomputed emb@W_ih[:, :E]^T + b_ih + b_hh
__device__ float g_capemb[Bb * Tt * Ee];
__device__ float g_outs[Bb * Tt * Oo];
__device__ float g_gates[Bb * Gg];
__device__ float g_WkT[Cc * Uu];           // W_key transposed: g_WkT[c*U + u] = W_key[u*C + c]

// ---------------- transpose W_key (U,C) -> (C,U) ------------------------------
__global__ void k_transpose(const float* __restrict__ Wk) {
    __shared__ float tile[32][33];
    int u0 = blockIdx.x * 32;
    int c0 = blockIdx.y * 32;
    int tx = threadIdx.x, ty = threadIdx.y;      // 32x8
#pragma unroll
    for (int r = 0; r < 32; r += 8)
        tile[ty + r][tx] = Wk[(size_t)(u0 + ty + r) * Cc + c0 + tx];
    __syncthreads();
#pragma unroll
    for (int r = 0; r < 32; r += 8)
        g_WkT[(size_t)(c0 + ty + r) * Uu + u0 + tx] = tile[tx][ty + r];
}

// ---------------- mean over HW ------------------------------------------------
__global__ void k_mean(const float* __restrict__ img) {
    int idx = blockIdx.x * blockDim.x + threadIdx.x;   // B*C = 32768
    if (idx >= Bb * Cc) return;
    const float4* p = (const float4*)(img + (size_t)idx * HW);
    float s = 0.f;
#pragma unroll
    for (int i = 0; i < HW / 4; i++) { float4 v = p[i]; s += v.x + v.y + v.z + v.w; }
    g_mean[idx] = s * (1.0f / HW);
}

// ---------------- embedding gather + max_norm renorm --------------------------
__global__ void k_emb(const float* __restrict__ emb, const int* __restrict__ ix) {
    int bt = blockIdx.x;                  // 0..B*T-1
    int row = ix[bt];
    const float* e = emb + (size_t)row * Ee;
    int tid = threadIdx.x;                // 64 threads
    float v[4];
    float ss = 0.f;
#pragma unroll
    for (int i = 0; i < 4; i++) { v[i] = e[tid + 64 * i]; ss += v[i] * v[i]; }
#pragma unroll
    for (int o = 16; o > 0; o >>= 1) ss += __shfl_xor_sync(0xffffffffu, ss, o);
    __shared__ float red[2];
    if ((tid & 31) == 0) red[tid >> 5] = ss;
    __syncthreads();
    float norm = sqrtf(red[0] + red[1]);
    float sc = fminf(1.0f, 5.0f / fmaxf(norm, 1e-12f));
#pragma unroll
    for (int i = 0; i < 4; i++) g_capemb[bt * Ee + tid + 64 * i] = v[i] * sc;
}

// ---------------- generic C = [Cinit +] A@W^T [+ A2@W2^T] [+ bias] -----------
// A [M,K] row-major, W rows are output columns (x@W^T pattern), both K-contig.
// Tile: 64(M) x 16(N) x 32(K). 256 threads; thread -> (m = tid&63, 4 n's).
__global__ void k_gemm(const float* __restrict__ A,  int lda,
                       const float* __restrict__ W,  int ldw,  int wc0,  int K1,
                       const float* __restrict__ A2, int lda2,
                       const float* __restrict__ W2, int ldw2, int wc02, int K2,
                       const float* __restrict__ Cinit, int ldci,
                       const float* __restrict__ bias0,
                       const float* __restrict__ bias1,
                       float* __restrict__ Cd, int ldc) {
    __shared__ float As[32][65];
    __shared__ float Ws[32][16];

    int tid = threadIdx.x;
    int m0 = blockIdx.y * 64;
    int n0 = blockIdx.x * 16;
    int m  = tid & 63;
    int nq = tid >> 6;                    // 0..3
    int nbase = n0 + nq * 4;

    float acc[4];
    if (Cinit) {
        float4 ci = *(const float4*)(Cinit + (size_t)(m0 + m) * ldci + nbase);
        acc[0] = ci.x; acc[1] = ci.y; acc[2] = ci.z; acc[3] = ci.w;
    } else {
        acc[0] = acc[1] = acc[2] = acc[3] = 0.f;
    }

    const float* Aps[2] = {A, A2};
    const float* Wps[2] = {W, W2};
    int ldAs[2] = {lda, lda2};
    int ldWs[2] = {ldw, ldw2};
    int w0s[2]  = {wc0, wc02};
    int Ks[2]   = {K1, K2};

#pragma unroll
    for (int ph = 0; ph < 2; ph++) {
        const float* Ap = Aps[ph];
        if (Ap == nullptr) continue;
        const float* Wp = Wps[ph];
        int ldA = ldAs[ph], ldW = ldWs[ph], w0 = w0s[ph], K = Ks[ph];
        for (int kc = 0; kc < K; kc += 32) {
            // A chunk 64x32 -> As[k][m], 2 float4 per thread
#pragma unroll
            for (int rep = 0; rep < 2; rep++) {
                int ff  = tid + rep * 256;
                int row = ff >> 3, kq = ff & 7;
                float4 v = *(const float4*)(Ap + (size_t)(m0 + row) * ldA + kc + kq * 4);
                As[kq * 4 + 0][row] = v.x;
                As[kq * 4 + 1][row] = v.y;
                As[kq * 4 + 2][row] = v.z;
                As[kq * 4 + 3][row] = v.w;
            }
            // W chunk 16x32 -> Ws[k][n], 1 float2 per thread
            {
                int row = tid >> 4, kq = tid & 15;
                float2 v = *(const float2*)(Wp + (size_t)(n0 + row) * ldW + w0 + kc + kq * 2);
                Ws[kq * 2 + 0][row] = v.x;
                Ws[kq * 2 + 1][row] = v.y;
            }
            __syncthreads();
#pragma unroll
            for (int k = 0; k < 32; k++) {
                float av = As[k][m];
                float4 w4 = *(const float4*)&Ws[k][nq * 4];
                acc[0] += av * w4.x;
                acc[1] += av * w4.y;
                acc[2] += av * w4.z;
                acc[3] += av * w4.w;
            }
            __syncthreads();
        }
    }

    float bb0 = 0.f, bb1 = 0.f, bb2 = 0.f, bb3 = 0.f;
    if (bias0) { bb0 += bias0[nbase]; bb1 += bias0[nbase + 1]; bb2 += bias0[nbase + 2]; bb3 += bias0[nbase + 3]; }
    if (bias1) { bb0 += bias1[nbase]; bb1 += bias1[nbase + 1]; bb2 += bias1[nbase + 2]; bb3 += bias1[nbase + 3]; }
    float4 o4 = make_float4(acc[0] + bb0, acc[1] + bb1, acc[2] + bb2, acc[3] + bb3);
    *(float4*)(Cd + (size_t)(m0 + m) * ldc + nbase) = o4;
}

// ---------------- per-step attention: scores -> softmax -> context ------------
__global__ void k_attn(const float* __restrict__ img, float* __restrict__ attn_out, int t) {
    int b = blockIdx.x;
    int tid = threadIdx.x;                 // 256
    __shared__ float qs[Cc];
    __shared__ float w_sh[HW];
    __shared__ float red[8];

    qs[tid]       = g_q[b * Cc + tid];
    qs[tid + 256] = g_q[b * Cc + tid + 256];
    __syncthreads();

    const float* ib = img + (size_t)b * Cc * HW;
    float s = -1e30f;
    if (tid < HW) {
        float a0 = 0.f, a1 = 0.f, a2 = 0.f, a3 = 0.f;
#pragma unroll 4
        for (int c = 0; c < Cc; c += 4) {
            a0 += qs[c + 0] * ib[(c + 0) * HW + tid];
            a1 += qs[c + 1] * ib[(c + 1) * HW + tid];
            a2 += qs[c + 2] * ib[(c + 2) * HW + tid];
            a3 += qs[c + 3] * ib[(c + 3) * HW + tid];
        }
        s = (a0 + a1 + a2 + a3) * 0.044194173824159216f;   // 1/sqrt(512)
    }
    float mx = s;
#pragma unroll
    for (int o = 16; o > 0; o >>= 1) mx = fmaxf(mx, __shfl_xor_sync(0xffffffffu, mx, o));
    if ((tid & 31) == 0) red[tid >> 5] = mx;
    __syncthreads();
    float mmax = red[0];
#pragma unroll
    for (int i = 1; i < 8; i++) mmax = fmaxf(mmax, red[i]);
    __syncthreads();
    float ev = (tid < HW) ? expf(s - mmax) : 0.f;
    float sm = ev;
#pragma unroll
    for (int o = 16; o > 0; o >>= 1) sm += __shfl_xor_sync(0xffffffffu, sm, o);
    if ((tid & 31) == 0) red[tid >> 5] = sm;
    __syncthreads();
    float total = red[0];
#pragma unroll
    for (int i = 1; i < 8; i++) total += red[i];
    float inv = 1.0f / total;
    if (tid < HW) {
        float w = ev * inv;
        w_sh[tid] = w;
        attn_out[((size_t)(b * Tt + t)) * HW + tid] = w;
    }
    __syncthreads();

    int wid = tid >> 5, lane = tid & 31;
    for (int c = wid; c < Cc; c += 8) {
        const float* rowp = ib + (size_t)c * HW;
        float acc = 0.f;
        for (int k = lane; k < HW; k += 32) acc += w_sh[k] * rowp[k];
#pragma unroll
        for (int o = 16; o > 0; o >>= 1) acc += __shfl_xor_sync(0xffffffffu, acc, o);
        if (lane == 0) g_a[b * Cc + c] = acc;
    }
}

// ---------------- LSTM pointwise + writeback of outs row ----------------------
__global__ void k_lstm(int t) {
    int b = blockIdx.x;
    int u = threadIdx.x;                  // 512
    float gi = g_gates[b * Gg + u];
    float gf = g_gates[b * Gg + Uu + u];
    float gg = g_gates[b * Gg + 2 * Uu + u];
    float go = g_gates[b * Gg + 3 * Uu + u];
    float cell = g_cell[b * Uu + u];
    float si = 1.f / (1.f + expf(-gi));
    float sf = 1.f / (1.f + expf(-gf));
    float so = 1.f / (1.f + expf(-go));
    float c2 = sf * cell + si * tanhf(gg);
    float h2 = so * tanhf(c2);
    g_cell[b * Uu + u] = c2;
    g_hid[b * Uu + u]  = h2;
    float* orow = g_outs + (size_t)(b * Tt + t) * Oo;
    orow[u]       = h2;                                 // hid
    orow[Uu + u]  = g_a[b * Cc + u];                    // a
    if (u < Ee) orow[Uu + Cc + u] = g_capemb[(b * Tt + t) * Ee + u];  // emb_t
}

// ---------------- logits = outs @ W_out^T + b_out (M=1280, N=10000, K=1280) ---
__global__ void k_logits(const float* __restrict__ Wout, const float* __restrict__ bout,
                         float* __restrict__ out) {
    __shared__ float As[8][132];
    __shared__ float Bs[8][132];
    int tid = threadIdx.x;
    int n0 = blockIdx.x * 128;
    int m0 = blockIdx.y * 128;
    int tm = (tid & 15) * 8;
    int tn = (tid >> 4) * 8;

    float acc[8][8];
#pragma unroll
    for (int i = 0; i < 8; i++)
#pragma unroll
        for (int j = 0; j < 8; j++) acc[i][j] = 0.f;

    int lr = tid >> 1;              // 0..127
    int lk = (tid & 1) * 4;         // 0 or 4
    const float* Aptr = g_outs + (size_t)(m0 + lr) * Oo + lk;
    int brow = n0 + lr;
    bool bok = brow < Vv;
    const float* Bptr = Wout + (size_t)(bok ? brow : 0) * Oo + lk;

    for (int kc = 0; kc < Oo; kc += 8) {
        float4 av = *(const float4*)(Aptr + kc);
        float4 bv = bok ? *(const float4*)(Bptr + kc) : make_float4(0.f, 0.f, 0.f, 0.f);
        As[lk + 0][lr] = av.x; As[lk + 1][lr] = av.y; As[lk + 2][lr] = av.z; As[lk + 3][lr] = av.w;
        Bs[lk + 0][lr] = bv.x; Bs[lk + 1][lr] = bv.y; Bs[lk + 2][lr] = bv.z; Bs[lk + 3][lr] = bv.w;
        __syncthreads();
#pragma unroll
        for (int k = 0; k < 8; k++) {
            float4 x0 = *(const float4*)&As[k][tm];
            float4 x1 = *(const float4*)&As[k][tm + 4];
            float4 y0 = *(const float4*)&Bs[k][tn];
            float4 y1 = *(const float4*)&Bs[k][tn + 4];
            float a8[8] = {x0.x, x0.y, x0.z, x0.w, x1.x, x1.y, x1.z, x1.w};
            float b8[8] = {y0.x, y0.y, y0.z, y0.w, y1.x, y1.y, y1.z, y1.w};
#pragma unroll
            for (int i = 0; i < 8; i++)
#pragma unroll
                for (int j = 0; j < 8; j++) acc[i][j] += a8[i] * b8[j];
        }
        __syncthreads();
    }

#pragma unroll
    for (int i = 0; i < 8; i++) {
        int mrow = m0 + tm + i;
#pragma unroll
        for (int j = 0; j < 8; j++) {
            int n = n0 + tn + j;
            if (n < Vv) out[(size_t)mrow * Vv + n] = acc[i][j] + bout[n];
        }
    }
}

// ---------------- launch ------------------------------------------------------
extern "C" void kernel_launch(void* const* d_in, const int* in_sizes, int n_in,
                              void* d_out, int out_size) {
    const float* img   = (const float*)d_in[0];
    const int*   cap   = (const int*)d_in[1];
    const float* W_h0  = (const float*)d_in[2];
    const float* b_h0  = (const float*)d_in[3];
    const float* W_c0  = (const float*)d_in[4];
    const float* b_c0  = (const float*)d_in[5];
    const float* emb   = (const float*)d_in[6];
    const float* W_key = (const float*)d_in[7];
    // b_key (d_in[8]) shifts scores by a k-independent constant -> softmax-invariant; skipped.
    const float* W_ih  = (const float*)d_in[9];
    const float* b_ih  = (const float*)d_in[10];
    const float* W_hh  = (const float*)d_in[11];
    const float* b_hh  = (const float*)d_in[12];
    const float* W_out = (const float*)d_in[13];
    const float* b_out = (const float*)d_in[14];

    float* logits = (float*)d_out;
    float* attn   = logits + (size_t)Bb * Tt * Vv;

    float *p_mean, *p_hid, *p_cell, *p_q, *p_a, *p_P, *p_capemb, *p_gates, *p_WkT;
    cudaGetSymbolAddress((void**)&p_mean,   g_mean);
    cudaGetSymbolAddress((void**)&p_hid,    g_hid);
    cudaGetSymbolAddress((void**)&p_cell,   g_cell);
    cudaGetSymbolAddress((void**)&p_q,      g_q);
    cudaGetSymbolAddress((void**)&p_a,      g_a);
    cudaGetSymbolAddress((void**)&p_P,      g_P);
    cudaGetSymbolAddress((void**)&p_capemb, g_capemb);
    cudaGetSymbolAddress((void**)&p_gates,  g_gates);
    cudaGetSymbolAddress((void**)&p_WkT,    g_WkT);

    k_transpose<<<dim3(Uu / 32, Cc / 32), dim3(32, 8)>>>(W_key);
    k_mean<<<128, 256>>>(img);
    k_emb<<<Bb * Tt, 64>>>(emb, cap);

    // hid0 / cell0: [64,512] = mean @ W^T + b   (M=64,N=512,K=512)
    k_gemm<<<dim3(Uu / 16, 1), 256>>>(p_mean, Cc, W_h0, Cc, 0, Cc,
                                      nullptr, 0, nullptr, 0, 0, 0,
                                      nullptr, 0, b_h0, nullptr, p_hid, Uu);
    k_gemm<<<dim3(Uu / 16, 1), 256>>>(p_mean, Cc, W_c0, Cc, 0, Cc,
                                      nullptr, 0, nullptr, 0, 0, 0,
                                      nullptr, 0, b_c0, nullptr, p_cell, Uu);

    // P[b,t,:] = cap_emb @ W_ih[:, :E]^T + b_ih + b_hh   (M=1280,N=2048,K=256)
    k_gemm<<<dim3(Gg / 16, (Bb * Tt) / 64), 256>>>(p_capemb, Ee, W_ih, Cc + Ee, 0, Ee,
                                                   nullptr, 0, nullptr, 0, 0, 0,
                                                   nullptr, 0, b_ih, b_hh, p_P, Gg);

    for (int t = 0; t < Tt; t++) {
        // q = hid @ W_key = hid @ (WkT)^T   (M=64,N=512,K=512)
        k_gemm<<<dim3(Cc / 16, 1), 256>>>(p_hid, Uu, p_WkT, Uu, 0, Uu,
                                          nullptr, 0, nullptr, 0, 0, 0,
                                          nullptr, 0, nullptr, nullptr, p_q, Cc);
        k_attn<<<Bb, 256>>>(img, attn, t);
        // gates = P_t + a @ W_ih[:, E:]^T + hid @ W_hh^T   (M=64,N=2048,K=512+512)
        k_gemm<<<dim3(Gg / 16, 1), 256>>>(p_a, Cc, W_ih, Cc + Ee, Ee, Cc,
                                          p_hid, Uu, W_hh, Uu, 0, Uu,
                                          p_P + t * Gg, Tt * Gg,
                                          nullptr, nullptr, p_gates, Gg);
        k_lstm<<<Bb, Uu>>>(t);
    }

    // logits = outs @ W_out^T + b_out   (M=1280, N=10000, K=1280)
    k_logits<<<dim3((Vv + 127) / 128, (Bb * Tt) / 128), 256>>>(W_out, b_out, logits);
}

// round 6
// speedup vs baseline: 1.2529x; 1.2529x over previous
#include <cuda_runtime.h>
#include <math.h>
#include <stdint.h>

#define Bb 64
#define Tt 20
#define Cc 512
#define HW 196
#define Vv 10000
#define Ee 256
#define Uu 512
#define Gg 2048   // 4*U
#define Oo 1280   // U + C + E

// ---------------- scratch (device globals; no runtime allocation) -------------
__device__ float g_mean[Bb * Cc];
__device__ float g_hid[Bb * Uu];
__device__ float g_cell[Bb * Uu];
__device__ float g_q[Bb * Cc];
__device__ float g_a[Bb * Cc];
__device__ float g_P[Bb * Tt * Gg];
__device__ float g_capemb[Bb * Tt * Ee];
__device__ float g_outs[Bb * Tt * Oo];
__device__ float g_gates[Bb * Gg];
__device__ float g_WkT[Cc * Uu];

__device__ __forceinline__ uint32_t f2tf(float x) {
    uint32_t r; asm("cvt.rna.tf32.f32 %0, %1;" : "=r"(r) : "f"(x)); return r;
}
__device__ __forceinline__ float f2tff(float x) { return __uint_as_float(f2tf(x)); }

__device__ __forceinline__ void mma_tf32(float* d, const uint32_t* a, const uint32_t* b) {
    asm volatile("mma.sync.aligned.m16n8k8.row.col.f32.tf32.tf32.f32 "
        "{%0,%1,%2,%3}, {%4,%5,%6,%7}, {%8,%9}, {%0,%1,%2,%3};"
        : "+f"(d[0]), "+f"(d[1]), "+f"(d[2]), "+f"(d[3])
        : "r"(a[0]), "r"(a[1]), "r"(a[2]), "r"(a[3]), "r"(b[0]), "r"(b[1]));
}

// ---------------- transpose W_key (U,C) -> (C,U) ------------------------------
__global__ void k_transpose(const float* __restrict__ Wk) {
    __shared__ float tile[32][33];
    int u0 = blockIdx.x * 32;
    int c0 = blockIdx.y * 32;
    int tx = threadIdx.x, ty = threadIdx.y;      // 32x8
#pragma unroll
    for (int r = 0; r < 32; r += 8)
        tile[ty + r][tx] = Wk[(size_t)(u0 + ty + r) * Cc + c0 + tx];
    __syncthreads();
#pragma unroll
    for (int r = 0; r < 32; r += 8)
        g_WkT[(size_t)(c0 + ty + r) * Uu + u0 + tx] = tile[tx][ty + r];
}

// ---------------- mean over HW ------------------------------------------------
__global__ void k_mean(const float* __restrict__ img) {
    int idx = blockIdx.x * blockDim.x + threadIdx.x;   // B*C = 32768
    if (idx >= Bb * Cc) return;
    const float4* p = (const float4*)(img + (size_t)idx * HW);
    float s = 0.f;
#pragma unroll
    for (int i = 0; i < HW / 4; i++) { float4 v = p[i]; s += v.x + v.y + v.z + v.w; }
    g_mean[idx] = s * (1.0f / HW);
}

// ---------------- embedding gather + max_norm renorm --------------------------
__global__ void k_emb(const float* __restrict__ emb, const int* __restrict__ ix) {
    int bt = blockIdx.x;
    int row = ix[bt];
    const float* e = emb + (size_t)row * Ee;
    int tid = threadIdx.x;                // 64 threads
    float v[4];
    float ss = 0.f;
#pragma unroll
    for (int i = 0; i < 4; i++) { v[i] = e[tid + 64 * i]; ss += v[i] * v[i]; }
#pragma unroll
    for (int o = 16; o > 0; o >>= 1) ss += __shfl_xor_sync(0xffffffffu, ss, o);
    __shared__ float red[2];
    if ((tid & 31) == 0) red[tid >> 5] = ss;
    __syncthreads();
    float norm = sqrtf(red[0] + red[1]);
    float sc = fminf(1.0f, 5.0f / fmaxf(norm, 1e-12f));
#pragma unroll
    for (int i = 0; i < 4; i++) g_capemb[bt * Ee + tid + 64 * i] = v[i] * sc;
}

// ---------------- generic C = [Cinit +] A@W^T [+ A2@W2^T] [+ bias] -----------
// Tile 64(M) x 16(N) x 32(K), 256 threads, register-prefetched K pipeline.
__global__ void k_gemm(const float* __restrict__ A,  int lda,
                       const float* __restrict__ W,  int ldw,  int wc0,  int K1,
                       const float* __restrict__ A2, int lda2,
                       const float* __restrict__ W2, int ldw2, int wc02, int K2,
                       const float* __restrict__ Cinit, int ldci,
                       const float* __restrict__ bias0,
                       const float* __restrict__ bias1,
                       float* __restrict__ Cd, int ldc) {
    __shared__ float As[32][65];
    __shared__ float Ws[32][16];

    int tid = threadIdx.x;
    int m0 = blockIdx.y * 64;
    int n0 = blockIdx.x * 16;
    int m  = tid & 63;
    int nq = tid >> 6;
    int nbase = n0 + nq * 4;

    // per-thread staging coordinates
    int ar0 = tid >> 3,        aq0 = tid & 7;           // rep 0
    int ar1 = (tid + 256) >> 3, aq1 = (tid + 256) & 7;  // rep 1
    int wr  = tid >> 4,        wq  = tid & 15;

    float acc[4];
    if (Cinit) {
        float4 ci = *(const float4*)(Cinit + (size_t)(m0 + m) * ldci + nbase);
        acc[0] = ci.x; acc[1] = ci.y; acc[2] = ci.z; acc[3] = ci.w;
    } else {
        acc[0] = acc[1] = acc[2] = acc[3] = 0.f;
    }

    const float* Aps[2] = {A, A2};
    const float* Wps[2] = {W, W2};
    int ldAs[2] = {lda, lda2};
    int ldWs[2] = {ldw, ldw2};
    int w0s[2]  = {wc0, wc02};
    int Ks[2]   = {K1, K2};

#pragma unroll
    for (int ph = 0; ph < 2; ph++) {
        const float* Ap = Aps[ph];
        if (Ap == nullptr) continue;
        const float* Wp = Wps[ph];
        int ldA = ldAs[ph], ldW = ldWs[ph], w0 = w0s[ph], K = Ks[ph];

        // preload chunk 0 into registers
        float4 pa0 = *(const float4*)(Ap + (size_t)(m0 + ar0) * ldA + aq0 * 4);
        float4 pa1 = *(const float4*)(Ap + (size_t)(m0 + ar1) * ldA + aq1 * 4);
        float2 pw  = *(const float2*)(Wp + (size_t)(n0 + wr) * ldW + w0 + wq * 2);

        for (int kc = 0; kc < K; kc += 32) {
            As[aq0 * 4 + 0][ar0] = pa0.x; As[aq0 * 4 + 1][ar0] = pa0.y;
            As[aq0 * 4 + 2][ar0] = pa0.z; As[aq0 * 4 + 3][ar0] = pa0.w;
            As[aq1 * 4 + 0][ar1] = pa1.x; As[aq1 * 4 + 1][ar1] = pa1.y;
            As[aq1 * 4 + 2][ar1] = pa1.z; As[aq1 * 4 + 3][ar1] = pa1.w;
            Ws[wq * 2 + 0][wr] = pw.x;    Ws[wq * 2 + 1][wr] = pw.y;
            __syncthreads();
            if (kc + 32 < K) {
                int kn = kc + 32;
                pa0 = *(const float4*)(Ap + (size_t)(m0 + ar0) * ldA + kn + aq0 * 4);
                pa1 = *(const float4*)(Ap + (size_t)(m0 + ar1) * ldA + kn + aq1 * 4);
                pw  = *(const float2*)(Wp + (size_t)(n0 + wr) * ldW + w0 + kn + wq * 2);
            }
#pragma unroll
            for (int k = 0; k < 32; k++) {
                float av = As[k][m];
                float4 w4 = *(const float4*)&Ws[k][nq * 4];
                acc[0] += av * w4.x;
                acc[1] += av * w4.y;
                acc[2] += av * w4.z;
                acc[3] += av * w4.w;
            }
            __syncthreads();
        }
    }

    float bb0 = 0.f, bb1 = 0.f, bb2 = 0.f, bb3 = 0.f;
    if (bias0) { bb0 += bias0[nbase]; bb1 += bias0[nbase + 1]; bb2 += bias0[nbase + 2]; bb3 += bias0[nbase + 3]; }
    if (bias1) { bb0 += bias1[nbase]; bb1 += bias1[nbase + 1]; bb2 += bias1[nbase + 2]; bb3 += bias1[nbase + 3]; }
    float4 o4 = make_float4(acc[0] + bb0, acc[1] + bb1, acc[2] + bb2, acc[3] + bb3);
    *(float4*)(Cd + (size_t)(m0 + m) * ldc + nbase) = o4;
}

// ---------------- per-step attention ------------------------------------------
__global__ void k_attn(const float* __restrict__ img, float* __restrict__ attn_out, int t) {
    int b = blockIdx.x;
    int tid = threadIdx.x;                 // 256
    __shared__ float qs[Cc];
    __shared__ float w_sh[HW];
    __shared__ float red[8];

    qs[tid]       = g_q[b * Cc + tid];
    qs[tid + 256] = g_q[b * Cc + tid + 256];
    __syncthreads();

    const float* ib = img + (size_t)b * Cc * HW;
    float s = -1e30f;
    if (tid < HW) {
        float a0 = 0.f, a1 = 0.f, a2 = 0.f, a3 = 0.f;
#pragma unroll 4
        for (int c = 0; c < Cc; c += 4) {
            a0 += qs[c + 0] * ib[(c + 0) * HW + tid];
            a1 += qs[c + 1] * ib[(c + 1) * HW + tid];
            a2 += qs[c + 2] * ib[(c + 2) * HW + tid];
            a3 += qs[c + 3] * ib[(c + 3) * HW + tid];
        }
        s = (a0 + a1 + a2 + a3) * 0.044194173824159216f;
    }
    float mx = s;
#pragma unroll
    for (int o = 16; o > 0; o >>= 1) mx = fmaxf(mx, __shfl_xor_sync(0xffffffffu, mx, o));
    if ((tid & 31) == 0) red[tid >> 5] = mx;
    __syncthreads();
    float mmax = red[0];
#pragma unroll
    for (int i = 1; i < 8; i++) mmax = fmaxf(mmax, red[i]);
    __syncthreads();
    float ev = (tid < HW) ? expf(s - mmax) : 0.f;
    float sm = ev;
#pragma unroll
    for (int o = 16; o > 0; o >>= 1) sm += __shfl_xor_sync(0xffffffffu, sm, o);
    if ((tid & 31) == 0) red[tid >> 5] = sm;
    __syncthreads();
    float total = red[0];
#pragma unroll
    for (int i = 1; i < 8; i++) total += red[i];
    float inv = 1.0f / total;
    if (tid < HW) {
        float w = ev * inv;
        w_sh[tid] = w;
        attn_out[((size_t)(b * Tt + t)) * HW + tid] = w;
    }
    __syncthreads();

    int wid = tid >> 5, lane = tid & 31;
    for (int c = wid; c < Cc; c += 8) {
        const float* rowp = ib + (size_t)c * HW;
        float acc = 0.f;
        for (int k = lane; k < HW; k += 32) acc += w_sh[k] * rowp[k];
#pragma unroll
        for (int o = 16; o > 0; o >>= 1) acc += __shfl_xor_sync(0xffffffffu, acc, o);
        if (lane == 0) g_a[b * Cc + c] = acc;
    }
}

// ---------------- LSTM pointwise + writeback of outs row ----------------------
__global__ void k_lstm(int t) {
    int b = blockIdx.x;
    int u = threadIdx.x;                  // 512
    float gi = g_gates[b * Gg + u];
    float gf = g_gates[b * Gg + Uu + u];
    float gg = g_gates[b * Gg + 2 * Uu + u];
    float go = g_gates[b * Gg + 3 * Uu + u];
    float cell = g_cell[b * Uu + u];
    float si = 1.f / (1.f + expf(-gi));
    float sf = 1.f / (1.f + expf(-gf));
    float so = 1.f / (1.f + expf(-go));
    float c2 = sf * cell + si * tanhf(gg);
    float h2 = so * tanhf(c2);
    g_cell[b * Uu + u] = c2;
    g_hid[b * Uu + u]  = h2;
    float* orow = g_outs + (size_t)(b * Tt + t) * Oo;
    orow[u]       = h2;
    orow[Uu + u]  = g_a[b * Cc + u];
    if (u < Ee) orow[Uu + Cc + u] = g_capemb[(b * Tt + t) * Ee + u];
}

// ===== logits via warp-level tf32 mma: outs[1280,1280] @ W_out[10000,1280]^T ===
// Block 128x128, 8 warps (2x4), warp tile 64x32, K chunk 32, double buffer.
// smem pitch 36 floats -> fragment LDS bank = (4*row+col)%32, conflict-free.
#define LPITCH 36
#define LSTAGE (128 * LPITCH * 2)          // floats per stage (A then B)
#define LSMEM_BYTES (2 * LSTAGE * 4)       // 73728 B

__global__ void __launch_bounds__(256, 1)
k_logits_mma(const float* __restrict__ Wout, const float* __restrict__ bout,
             float* __restrict__ out) {
    extern __shared__ float sm[];
    int tid = threadIdx.x;
    int wid = tid >> 5, lane = tid & 31;
    int r = lane >> 2, c = lane & 3;
    int n0 = blockIdx.x * 128;
    int m0 = blockIdx.y * 128;
    int m0w = (wid & 1) * 64;
    int n0w = (wid >> 1) * 32;

    float acc[4][4][4];
#pragma unroll
    for (int i = 0; i < 4; i++)
#pragma unroll
        for (int j = 0; j < 4; j++)
#pragma unroll
            for (int k = 0; k < 4; k++) acc[i][j][k] = 0.f;

    // staging coords: 4 float4 per thread per matrix
    int srow[4], sq[4];
#pragma unroll
    for (int i = 0; i < 4; i++) { int f = tid + i * 256; srow[i] = f >> 3; sq[i] = f & 7; }

    // preload chunk 0
    float4 pa[4], pb[4];
#pragma unroll
    for (int i = 0; i < 4; i++) {
        pa[i] = *(const float4*)(g_outs + (size_t)(m0 + srow[i]) * Oo + sq[i] * 4);
        int n = n0 + srow[i];
        pb[i] = (n < Vv) ? *(const float4*)(Wout + (size_t)n * Oo + sq[i] * 4)
                         : make_float4(0.f, 0.f, 0.f, 0.f);
    }

    for (int ch = 0; ch < Oo / 32; ++ch) {
        int st = ch & 1;
        float* Asb = sm + st * LSTAGE;
        float* Bsb = Asb + 128 * LPITCH;
        // store (with tf32 rounding)
#pragma unroll
        for (int i = 0; i < 4; i++) {
            float4 ta = make_float4(f2tff(pa[i].x), f2tff(pa[i].y), f2tff(pa[i].z), f2tff(pa[i].w));
            float4 tb = make_float4(f2tff(pb[i].x), f2tff(pb[i].y), f2tff(pb[i].z), f2tff(pb[i].w));
            *(float4*)(Asb + srow[i] * LPITCH + sq[i] * 4) = ta;
            *(float4*)(Bsb + srow[i] * LPITCH + sq[i] * 4) = tb;
        }
        __syncthreads();
        // prefetch next chunk
        if (ch + 1 < Oo / 32) {
            int kc = (ch + 1) * 32;
#pragma unroll
            for (int i = 0; i < 4; i++) {
                pa[i] = *(const float4*)(g_outs + (size_t)(m0 + srow[i]) * Oo + kc + sq[i] * 4);
                int n = n0 + srow[i];
                pb[i] = (n < Vv) ? *(const float4*)(Wout + (size_t)n * Oo + kc + sq[i] * 4)
                                 : make_float4(0.f, 0.f, 0.f, 0.f);
            }
        }
        // compute 4 x k8
#pragma unroll
        for (int kk = 0; kk < 4; kk++) {
            uint32_t af[4][4], bf[4][2];
#pragma unroll
            for (int mt = 0; mt < 4; mt++) {
                const float* p = Asb + (m0w + mt * 16 + r) * LPITCH + kk * 8 + c;
                af[mt][0] = __float_as_uint(p[0]);
                af[mt][1] = __float_as_uint(p[8 * LPITCH]);
                af[mt][2] = __float_as_uint(p[4]);
                af[mt][3] = __float_as_uint(p[8 * LPITCH + 4]);
            }
#pragma unroll
            for (int nt = 0; nt < 4; nt++) {
                const float* p = Bsb + (n0w + nt * 8 + r) * LPITCH + kk * 8 + c;
                bf[nt][0] = __float_as_uint(p[0]);
                bf[nt][1] = __float_as_uint(p[4]);
            }
#pragma unroll
            for (int mt = 0; mt < 4; mt++)
#pragma unroll
                for (int nt = 0; nt < 4; nt++)
                    mma_tf32(acc[mt][nt], af[mt], bf[nt]);
        }
        __syncthreads();
    }

    // epilogue: C layout c0:(r, 2c) c1:(r, 2c+1) c2:(r+8, 2c) c3:(r+8, 2c+1)
#pragma unroll
    for (int mt = 0; mt < 4; mt++) {
        int gr = m0 + m0w + mt * 16 + r;
#pragma unroll
        for (int nt = 0; nt < 4; nt++) {
            int gc = n0 + n0w + nt * 8 + c * 2;
            if (gc < Vv) {
                float2 bv = *(const float2*)(bout + gc);
                float2 o0 = make_float2(acc[mt][nt][0] + bv.x, acc[mt][nt][1] + bv.y);
                float2 o1 = make_float2(acc[mt][nt][2] + bv.x, acc[mt][nt][3] + bv.y);
                *(float2*)(out + (size_t)gr * Vv + gc) = o0;
                *(float2*)(out + (size_t)(gr + 8) * Vv + gc) = o1;
            }
        }
    }
}

// ---------------- launch ------------------------------------------------------
extern "C" void kernel_launch(void* const* d_in, const int* in_sizes, int n_in,
                              void* d_out, int out_size) {
    const float* img   = (const float*)d_in[0];
    const int*   cap   = (const int*)d_in[1];
    const float* W_h0  = (const float*)d_in[2];
    const float* b_h0  = (const float*)d_in[3];
    const float* W_c0  = (const float*)d_in[4];
    const float* b_c0  = (const float*)d_in[5];
    const float* emb   = (const float*)d_in[6];
    const float* W_key = (const float*)d_in[7];
    // b_key (d_in[8]) is softmax-invariant; skipped.
    const float* W_ih  = (const float*)d_in[9];
    const float* b_ih  = (const float*)d_in[10];
    const float* W_hh  = (const float*)d_in[11];
    const float* b_hh  = (const float*)d_in[12];
    const float* W_out = (const float*)d_in[13];
    const float* b_out = (const float*)d_in[14];

    float* logits = (float*)d_out;
    float* attn   = logits + (size_t)Bb * Tt * Vv;

    float *p_mean, *p_hid, *p_cell, *p_q, *p_a, *p_P, *p_capemb, *p_gates, *p_WkT;
    cudaGetSymbolAddress((void**)&p_mean,   g_mean);
    cudaGetSymbolAddress((void**)&p_hid,    g_hid);
    cudaGetSymbolAddress((void**)&p_cell,   g_cell);
    cudaGetSymbolAddress((void**)&p_q,      g_q);
    cudaGetSymbolAddress((void**)&p_a,      g_a);
    cudaGetSymbolAddress((void**)&p_P,      g_P);
    cudaGetSymbolAddress((void**)&p_capemb, g_capemb);
    cudaGetSymbolAddress((void**)&p_gates,  g_gates);
    cudaGetSymbolAddress((void**)&p_WkT,    g_WkT);

    k_transpose<<<dim3(Uu / 32, Cc / 32), dim3(32, 8)>>>(W_key);
    k_mean<<<128, 256>>>(img);
    k_emb<<<Bb * Tt, 64>>>(emb, cap);

    k_gemm<<<dim3(Uu / 16, 1), 256>>>(p_mean, Cc, W_h0, Cc, 0, Cc,
                                      nullptr, 0, nullptr, 0, 0, 0,
                                      nullptr, 0, b_h0, nullptr, p_hid, Uu);
    k_gemm<<<dim3(Uu / 16, 1), 256>>>(p_mean, Cc, W_c0, Cc, 0, Cc,
                                      nullptr, 0, nullptr, 0, 0, 0,
                                      nullptr, 0, b_c0, nullptr, p_cell, Uu);

    k_gemm<<<dim3(Gg / 16, (Bb * Tt) / 64), 256>>>(p_capemb, Ee, W_ih, Cc + Ee, 0, Ee,
                                                   nullptr, 0, nullptr, 0, 0, 0,
                                                   nullptr, 0, b_ih, b_hh, p_P, Gg);

    for (int t = 0; t < Tt; t++) {
        k_gemm<<<dim3(Cc / 16, 1), 256>>>(p_hid, Uu, p_WkT, Uu, 0, Uu,
                                          nullptr, 0, nullptr, 0, 0, 0,
                                          nullptr, 0, nullptr, nullptr, p_q, Cc);
        k_attn<<<Bb, 256>>>(img, attn, t);
        k_gemm<<<dim3(Gg / 16, 1), 256>>>(p_a, Cc, W_ih, Cc + Ee, Ee, Cc,
                                          p_hid, Uu, W_hh, Uu, 0, Uu,
                                          p_P + t * Gg, Tt * Gg,
                                          nullptr, nullptr, p_gates, Gg);
        k_lstm<<<Bb, Uu>>>(t);
    }

    // logits = outs @ W_out^T + b_out via tf32 mma.sync
    cudaFuncSetAttribute(k_logits_mma, cudaFuncAttributeMaxDynamicSharedMemorySize, LSMEM_BYTES);
    k_logits_mma<<<dim3((Vv + 127) / 128, (Bb * Tt) / 128), 256, LSMEM_BYTES>>>(W_out, b_out, logits);
}